// round 12
// baseline (speedup 1.0000x reference)
#include <cuda_runtime.h>
#include <cuda_bf16.h>
#include <math.h>
#include <stdint.h>

// ---------------- problem constants ----------------
#define NB       128
#define TLEN     160000
#define NFFT     400
#define HOP      160
#define NFRAMES  1001
#define NFREQ    201
#define NMELS    80

// ---------------- GEMM tiling (mma.sync m16n8k16 bf16) ----------------
#define MTILE    64                  // frames per CTA
#define FBLK     16                  // CTAs per batch
#define KT       13                  // k16 tiles (K = 208, n = 1..199 padded)
#define NT       28                  // n8 tiles (bins padded to 224)
#define NTHREADS 1024
#define SPAN     (HOP * (MTILE - 1) + NFFT)    // 10480
#define SWZ(i)   ((i) + ((i) >> 5))
#define PSTRIDE  209

// smem byte offsets
#define RAW_BYTES 43232              // SWZ(10479)+1 floats, padded
#define W_OFF    RAW_BYTES
#define A_OFF    (W_OFF + 1632)
#define APART_U32 (KT * 4 * 32 * 4)  // 6656 u32 per operand part
#define A_EHI    (A_OFF)
#define A_ELO    (A_EHI + APART_U32 * 4)
#define A_OHI    (A_ELO + APART_U32 * 4)
#define A_OLO    (A_OHI + APART_U32 * 4)
#define P_OFF    (A_OLO + APART_U32 * 4)
#define SMEM_TOTAL (P_OFF + MTILE * PSTRIDE * 4)   // 204864

// B tables, fragment layout, hi/lo interleaved per lane:
// g_Bc/g_Bs[((nt*13+kt)*32+lane)*4 + r], r = {0,1}: hi regs, {2,3}: lo regs
#define BTAB_U32 (NT * KT * 32 * 4)            // 46592
__device__ unsigned g_Bc[BTAB_U32];
__device__ unsigned g_Bs[BTAB_U32];
__device__ int2 g_mrange[NMELS];

__device__ __forceinline__ void bf_split(float v, unsigned short& hi, unsigned short& lo) {
    __nv_bfloat16 h = __float2bfloat16(v);
    hi = __bfloat16_as_ushort(h);
    lo = __bfloat16_as_ushort(__float2bfloat16(v - __bfloat162float(h)));
}

// ---------------- setup: B fragments + mel ranges ----------------
__global__ void setup_kernel(const float* __restrict__ fb) {
    if (blockIdx.x == gridDim.x - 1) {
        int m = threadIdx.x;
        if (m < NMELS) {
            int ks = NFREQ, ke = 0;
            for (int k = 0; k < NFREQ; k++)
                if (fb[m * NFREQ + k] != 0.0f) { if (k < ks) ks = k; ke = k + 1; }
            if (ke < ks) { ks = 0; ke = 0; }
            g_mrange[m] = make_int2(ks, ke);
        }
        return;
    }
    int id = blockIdx.x * blockDim.x + threadIdx.x;
    if (id >= 2 * BTAB_U32) return;
    int trig = id / BTAB_U32;
    int s    = id - trig * BTAB_U32;
    int r    = s & 3;                  // 0,1: hi pair regs; 2,3: lo pair regs
    int lane = (s >> 2) & 31;
    int t    = s >> 7;
    int kt   = t % 13;
    int nt   = t / 13;
    int reg  = r & 1;
    int part_lo = r >> 1;
    int p    = (reg << 2) | (lane & 3);    // k-pair index within k16 tile
    int col  = lane >> 2;
    int k0   = kt * 16 + 2 * p;
    int bin  = nt * 8 + col;
    unsigned short b0 = 0, b1 = 0;
    #pragma unroll
    for (int e = 0; e < 2; e++) {
        int n = k0 + e + 1;
        float v = 0.0f;
        if (n <= 199 && bin <= 200) {
            long long ph = ((long long)n * bin) % NFFT;
            double a = (double)ph * (6.283185307179586476925286766559 / (double)NFFT);
            v = (float)(trig ? sin(a) : cos(a));
        }
        unsigned short hi, lo;
        bf_split(v, hi, lo);
        unsigned short ev = part_lo ? lo : hi;
        if (e == 0) b0 = ev; else b1 = ev;
    }
    unsigned* dst = trig ? g_Bs : g_Bc;
    dst[s] = ((unsigned)b1 << 16) | b0;
}

#define MMA4(d, ax,ay,az,aw, bx,by) \
    asm volatile("mma.sync.aligned.m16n8k16.row.col.f32.bf16.bf16.f32 " \
        "{%0,%1,%2,%3}, {%4,%5,%6,%7}, {%8,%9}, {%0,%1,%2,%3};" \
        : "+f"((d)[0]), "+f"((d)[1]), "+f"((d)[2]), "+f"((d)[3]) \
        : "r"(ax), "r"(ay), "r"(az), "r"(aw), "r"(bx), "r"(by))

// ---------------- main kernel ----------------
__global__ __launch_bounds__(NTHREADS, 1)
void melspec_kernel(const float* __restrict__ audio,
                    const float* __restrict__ window,
                    const float* __restrict__ fb,
                    float* __restrict__ out) {
    extern __shared__ char smem[];
    float*    s_raw = (float*)smem;
    float*    s_w   = (float*)(smem + W_OFF);
    unsigned* a_ehi = (unsigned*)(smem + A_EHI);
    unsigned* a_elo = (unsigned*)(smem + A_ELO);
    unsigned* a_ohi = (unsigned*)(smem + A_OHI);
    unsigned* a_olo = (unsigned*)(smem + A_OLO);
    float*    s_p   = (float*)(smem + P_OFF);

    const int tid    = threadIdx.x;
    const int b      = blockIdx.y;
    const int frame0 = blockIdx.x * MTILE;
    const float* x   = audio + (size_t)b * TLEN;
    const int base   = frame0 * HOP - (NFFT / 2);

    // ---- raw samples (reflect pad, swizzled) + window ----
    for (int i = tid; i < SPAN; i += NTHREADS) {
        int j = base + i;
        if (j < 0) j = -j;
        else if (j >= TLEN) j = 2 * TLEN - 2 - j;
        s_raw[SWZ(i)] = x[j];
    }
    if (tid < NFFT) s_w[tid] = window[tid];
    __syncthreads();

    // ---- build A fragments: e/o, hi/lo, in mma lane layout ----
    {
        const int f   = tid >> 4;            // 0..63
        const int t16 = tid & 15;            // 16 threads per frame
        const int nb  = f * HOP;
        #pragma unroll
        for (int jj = 0; jj < 7; jj++) {
            int kq = t16 + 16 * jj;          // 0..111, valid < 104
            if (kq >= 104) break;
            int k0 = kq * 2;
            float e0 = 0.f, o0 = 0.f, e1 = 0.f, o1 = 0.f;
            int n0 = k0 + 1;
            if (n0 <= 199) {
                float w = s_w[n0];
                float a = s_raw[SWZ(nb + n0)], c = s_raw[SWZ(nb + NFFT - n0)];
                e0 = w * (a + c); o0 = w * (a - c);
            }
            int n1 = k0 + 2;
            if (n1 <= 199) {
                float w = s_w[n1];
                float a = s_raw[SWZ(nb + n1)], c = s_raw[SWZ(nb + NFFT - n1)];
                e1 = w * (a + c); o1 = w * (a - c);
            }
            unsigned short eh0, el0, eh1, el1, oh0, ol0, oh1, ol1;
            bf_split(e0, eh0, el0); bf_split(e1, eh1, el1);
            bf_split(o0, oh0, ol0); bf_split(o1, oh1, ol1);
            int kt   = k0 >> 4;
            int q    = (k0 >> 1) & 7;
            int lane = ((f & 7) << 2) | (q & 3);
            int reg  = ((f >> 3) & 1) | (((q >> 2) & 1) << 1);
            int mt   = f >> 4;
            int ai   = ((kt * 4 + mt) * 32 + lane) * 4 + reg;
            a_ehi[ai] = ((unsigned)eh1 << 16) | eh0;
            a_elo[ai] = ((unsigned)el1 << 16) | el0;
            a_ohi[ai] = ((unsigned)oh1 << 16) | oh0;
            a_olo[ai] = ((unsigned)ol1 << 16) | ol0;
        }
    }
    __syncthreads();

    // ---- GEMM: 1 m-tile x 4 n-tiles per warp (28 active warps) ----
    {
        const int w    = tid >> 5;
        const int lane = tid & 31;
        if (w < 28) {
            const int mt = w & 3;
            const int nq = w >> 2;            // nt = nq + 7*t
            float acc[4][8];
            #pragma unroll
            for (int t = 0; t < 4; t++)
                #pragma unroll
                for (int j = 0; j < 8; j++) acc[t][j] = 0.0f;

            for (int kt = 0; kt < KT; kt++) {
                int ai = ((kt * 4 + mt) * 32 + lane) * 4;
                uint4 Ae = *(const uint4*)(a_ehi + ai);
                uint4 Al = *(const uint4*)(a_elo + ai);
                uint4 Ao = *(const uint4*)(a_ohi + ai);
                uint4 Az = *(const uint4*)(a_olo + ai);
                #pragma unroll
                for (int t = 0; t < 4; t++) {
                    int nt = nq + 7 * t;
                    int bi = ((nt * KT + kt) * 32 + lane) * 4;
                    uint4 bc = *(const uint4*)(g_Bc + bi);
                    uint4 bs = *(const uint4*)(g_Bs + bi);
                    MMA4(acc[t],     Ae.x, Ae.y, Ae.z, Ae.w, bc.x, bc.y);
                    MMA4(acc[t],     Al.x, Al.y, Al.z, Al.w, bc.x, bc.y);
                    MMA4(acc[t],     Ae.x, Ae.y, Ae.z, Ae.w, bc.z, bc.w);
                    MMA4(acc[t] + 4, Ao.x, Ao.y, Ao.z, Ao.w, bs.x, bs.y);
                    MMA4(acc[t] + 4, Az.x, Az.y, Az.z, Az.w, bs.x, bs.y);
                    MMA4(acc[t] + 4, Ao.x, Ao.y, Ao.z, Ao.w, bs.z, bs.w);
                }
            }

            // epilogue: DC/Nyquist terms + power into smem
            const int fa  = mt * 16 + (lane >> 2);
            const int fb2 = fa + 8;
            float t0a   = s_w[0]   * s_raw[SWZ(fa  * HOP)];
            float t200a = s_w[200] * s_raw[SWZ(fa  * HOP + 200)];
            float t0b   = s_w[0]   * s_raw[SWZ(fb2 * HOP)];
            float t200b = s_w[200] * s_raw[SWZ(fb2 * HOP + 200)];
            #pragma unroll
            for (int t = 0; t < 4; t++) {
                int c0 = (nq + 7 * t) * 8 + ((lane & 3) << 1);
                float ra0 = acc[t][0] + t0a + t200a;
                float ra1 = acc[t][1] + t0a - t200a;
                float rb0 = acc[t][2] + t0b + t200b;
                float rb1 = acc[t][3] + t0b - t200b;
                if (c0 < NFREQ) {
                    s_p[fa  * PSTRIDE + c0] = ra0 * ra0 + acc[t][4] * acc[t][4];
                    s_p[fb2 * PSTRIDE + c0] = rb0 * rb0 + acc[t][6] * acc[t][6];
                }
                if (c0 + 1 < NFREQ) {
                    s_p[fa  * PSTRIDE + c0 + 1] = ra1 * ra1 + acc[t][5] * acc[t][5];
                    s_p[fb2 * PSTRIDE + c0 + 1] = rb1 * rb1 + acc[t][7] * acc[t][7];
                }
            }
        }
    }
    __syncthreads();

    // ---- sparse mel projection + log ----
    {
        const int f   = tid & (MTILE - 1);
        const int grp = tid >> 6;                 // 0..15
        int nvalid = NFRAMES - frame0;
        if (nvalid > MTILE) nvalid = MTILE;
        const float* prow = s_p + f * PSTRIDE;
        for (int m = grp; m < NMELS; m += 16) {
            int2 r = g_mrange[m];
            float acc = 0.0f;
            const float* fbr = fb + m * NFREQ;
            for (int kk = r.x; kk < r.y; kk++)
                acc = fmaf(fbr[kk], prow[kk], acc);
            if (f < nvalid)
                out[((size_t)b * NMELS + m) * NFRAMES + frame0 + f] =
                    logf(acc + 1.1920929e-07f);
        }
    }
}

extern "C" void kernel_launch(void* const* d_in, const int* in_sizes, int n_in,
                              void* d_out, int out_size) {
    const float* audio  = (const float*)d_in[0];
    const float* window = (const float*)d_in[1];
    const float* fb     = (const float*)d_in[2];
    float* out          = (float*)d_out;

    cudaFuncSetAttribute(melspec_kernel,
                         cudaFuncAttributeMaxDynamicSharedMemorySize, SMEM_TOTAL);

    int setup_blocks = (2 * BTAB_U32 + 255) / 256 + 1;
    setup_kernel<<<setup_blocks, 256>>>(fb);

    dim3 grid(FBLK, NB);
    melspec_kernel<<<grid, NTHREADS, SMEM_TOTAL>>>(audio, window, fb, out);
}

// round 14
// speedup vs baseline: 1.1497x; 1.1497x over previous
#include <cuda_runtime.h>
#include <cuda_bf16.h>
#include <math.h>
#include <stdint.h>

// ---------------- problem constants ----------------
#define NB       128
#define TLEN     160000
#define NFFT     400
#define HOP      160
#define NFRAMES  1001
#define NFREQ    201
#define NMELS    80

// ---------------- GEMM tiling (mma.sync m16n8k16 bf16) ----------------
#define MTILE    64                  // frames per CTA
#define FBLK     16                  // CTAs per batch
#define KT       13                  // k16 tiles (K = 208, n = 1..199 padded)
#define NT       28                  // n8 tiles (bins padded to 224)
#define NTHREADS 512
#define SPAN     (HOP * (MTILE - 1) + NFFT)    // 10480
#define SWZ(i)   ((i) + ((i) >> 5))
#define PSTRIDE  209

// smem byte offsets
#define RAW_BYTES 43232              // SWZ(10479)+1 floats, padded
#define W_OFF    RAW_BYTES
#define A_OFF    (W_OFF + 1632)
#define APART_U32 (KT * 4 * 32 * 4)  // 6656 u32 per operand part
#define A_EHI    (A_OFF)
#define A_ELO    (A_EHI + APART_U32 * 4)
#define A_OHI    (A_ELO + APART_U32 * 4)
#define A_OLO    (A_OHI + APART_U32 * 4)
#define P_OFF    (A_OLO + APART_U32 * 4)
#define SMEM_TOTAL (P_OFF + MTILE * PSTRIDE * 4)   // 204864

// Per-kt B slice staged in smem (overlays s_p region during GEMM):
// bc: [0, NT*128) u32, bs: [NT*128, 2*NT*128). 2*28*128*4 = 28672 B <= 53504 B.
#define BSLICE_U32   (NT * 32 * 4)             // 3584 u32 per table per kt
#define BSLICE_UINT4 (NT * 32)                 // 896 uint4 per table per kt

// B tables in global, kt-major fragment layout:
// g_Bc/g_Bs[((kt*NT + nt)*32 + lane)*4 + r], r = {0,1}: hi regs, {2,3}: lo regs
#define BTAB_U32 (NT * KT * 32 * 4)            // 46592
__device__ unsigned g_Bc[BTAB_U32];
__device__ unsigned g_Bs[BTAB_U32];
__device__ int2 g_mrange[NMELS];

__device__ __forceinline__ void bf_split(float v, unsigned short& hi, unsigned short& lo) {
    __nv_bfloat16 h = __float2bfloat16(v);
    hi = __bfloat16_as_ushort(h);
    lo = __bfloat16_as_ushort(__float2bfloat16(v - __bfloat162float(h)));
}

// ---------------- setup: B fragments + mel ranges ----------------
__global__ void setup_kernel(const float* __restrict__ fb) {
    if (blockIdx.x == gridDim.x - 1) {
        int m = threadIdx.x;
        if (m < NMELS) {
            int ks = NFREQ, ke = 0;
            for (int k = 0; k < NFREQ; k++)
                if (fb[m * NFREQ + k] != 0.0f) { if (k < ks) ks = k; ke = k + 1; }
            if (ke < ks) { ks = 0; ke = 0; }
            g_mrange[m] = make_int2(ks, ke);
        }
        return;
    }
    int id = blockIdx.x * blockDim.x + threadIdx.x;
    if (id >= 2 * BTAB_U32) return;
    int trig = id / BTAB_U32;
    int s    = id - trig * BTAB_U32;
    int r    = s & 3;                  // 0,1: hi pair regs; 2,3: lo pair regs
    int lane = (s >> 2) & 31;
    int t    = s >> 7;
    int kt   = t % 13;
    int nt   = t / 13;
    int reg  = r & 1;
    int part_lo = r >> 1;
    int p    = (reg << 2) | (lane & 3);    // k-pair index within k16 tile
    int col  = lane >> 2;
    int k0   = kt * 16 + 2 * p;
    int bin  = nt * 8 + col;
    unsigned short b0 = 0, b1 = 0;
    #pragma unroll
    for (int e = 0; e < 2; e++) {
        int n = k0 + e + 1;
        float v = 0.0f;
        if (n <= 199 && bin <= 200) {
            long long ph = ((long long)n * bin) % NFFT;
            double a = (double)ph * (6.283185307179586476925286766559 / (double)NFFT);
            v = (float)(trig ? sin(a) : cos(a));
        }
        unsigned short hi, lo;
        bf_split(v, hi, lo);
        unsigned short ev = part_lo ? lo : hi;
        if (e == 0) b0 = ev; else b1 = ev;
    }
    // kt-major destination so the per-kt slice is contiguous (coalesced staging)
    int dst_idx = ((kt * NT + nt) * 32 + lane) * 4 + r;
    unsigned* dst = trig ? g_Bs : g_Bc;
    dst[dst_idx] = ((unsigned)b1 << 16) | b0;
}

#define MMA4(d, ax,ay,az,aw, bx,by) \
    asm volatile("mma.sync.aligned.m16n8k16.row.col.f32.bf16.bf16.f32 " \
        "{%0,%1,%2,%3}, {%4,%5,%6,%7}, {%8,%9}, {%0,%1,%2,%3};" \
        : "+f"((d)[0]), "+f"((d)[1]), "+f"((d)[2]), "+f"((d)[3]) \
        : "r"(ax), "r"(ay), "r"(az), "r"(aw), "r"(bx), "r"(by))

// ---------------- main kernel ----------------
__global__ __launch_bounds__(NTHREADS, 1)
void melspec_kernel(const float* __restrict__ audio,
                    const float* __restrict__ window,
                    const float* __restrict__ fb,
                    float* __restrict__ out) {
    extern __shared__ char smem[];
    float*    s_raw = (float*)smem;
    float*    s_w   = (float*)(smem + W_OFF);
    unsigned* a_ehi = (unsigned*)(smem + A_EHI);
    unsigned* a_elo = (unsigned*)(smem + A_ELO);
    unsigned* a_ohi = (unsigned*)(smem + A_OHI);
    unsigned* a_olo = (unsigned*)(smem + A_OLO);
    float*    s_p   = (float*)(smem + P_OFF);
    unsigned* s_b   = (unsigned*)(smem + P_OFF);   // B staging (dead s_p region)

    const int tid    = threadIdx.x;
    const int b      = blockIdx.y;
    const int frame0 = blockIdx.x * MTILE;
    const float* x   = audio + (size_t)b * TLEN;
    const int base   = frame0 * HOP - (NFFT / 2);

    // ---- raw samples (reflect pad, swizzled) + window ----
    for (int i = tid; i < SPAN; i += NTHREADS) {
        int j = base + i;
        if (j < 0) j = -j;
        else if (j >= TLEN) j = 2 * TLEN - 2 - j;
        s_raw[SWZ(i)] = x[j];
    }
    if (tid < NFFT) s_w[tid] = window[tid];
    __syncthreads();

    // ---- build A fragments: e/o, hi/lo, in mma lane layout ----
    {
        const int f   = tid >> 3;            // 0..63
        const int kqb = (tid & 7) * 13;      // 13 kq per thread
        const int nb  = f * HOP;
        #pragma unroll
        for (int jj = 0; jj < 13; jj++) {
            int kq = kqb + jj;
            int k0 = kq * 2;
            float e0 = 0.f, o0 = 0.f, e1 = 0.f, o1 = 0.f;
            int n0 = k0 + 1;
            if (n0 <= 199) {
                float w = s_w[n0];
                float a = s_raw[SWZ(nb + n0)], c = s_raw[SWZ(nb + NFFT - n0)];
                e0 = w * (a + c); o0 = w * (a - c);
            }
            int n1 = k0 + 2;
            if (n1 <= 199) {
                float w = s_w[n1];
                float a = s_raw[SWZ(nb + n1)], c = s_raw[SWZ(nb + NFFT - n1)];
                e1 = w * (a + c); o1 = w * (a - c);
            }
            unsigned short eh0, el0, eh1, el1, oh0, ol0, oh1, ol1;
            bf_split(e0, eh0, el0); bf_split(e1, eh1, el1);
            bf_split(o0, oh0, ol0); bf_split(o1, oh1, ol1);
            int kt   = k0 >> 4;
            int q    = (k0 >> 1) & 7;
            int lane = ((f & 7) << 2) | (q & 3);
            int reg  = ((f >> 3) & 1) | (((q >> 2) & 1) << 1);
            int mt   = f >> 4;
            int ai   = ((kt * 4 + mt) * 32 + lane) * 4 + reg;
            a_ehi[ai] = ((unsigned)eh1 << 16) | eh0;
            a_elo[ai] = ((unsigned)el1 << 16) | el0;
            a_ohi[ai] = ((unsigned)oh1 << 16) | oh0;
            a_olo[ai] = ((unsigned)ol1 << 16) | ol0;
        }
    }

    // ---- GEMM: 2 m-tiles x 4 n-tiles per warp; B staged in smem per kt ----
    const int w    = tid >> 5;
    const int lane = tid & 31;
    const int mgrp = w & 1;            // m-tiles {2*mgrp, 2*mgrp+1}
    const int nq   = w >> 1;           // n-tiles nq*4 .. nq*4+3 (nq 0..6 active)

    float acc[2][4][8];
    #pragma unroll
    for (int mi = 0; mi < 2; mi++)
        #pragma unroll
        for (int t = 0; t < 4; t++)
            #pragma unroll
            for (int j = 0; j < 8; j++) acc[mi][t][j] = 0.0f;

    for (int kt = 0; kt < KT; kt++) {
        __syncthreads();        // A ready (kt==0) / previous MMA reads of s_b done
        // cooperative staging of B slice kt: bc then bs, contiguous uint4
        {
            const uint4* gc = (const uint4*)g_Bc + (size_t)kt * BSLICE_UINT4;
            const uint4* gs = (const uint4*)g_Bs + (size_t)kt * BSLICE_UINT4;
            uint4* sb = (uint4*)s_b;
            #pragma unroll
            for (int i = tid; i < 2 * BSLICE_UINT4; i += NTHREADS)
                sb[i] = (i < BSLICE_UINT4) ? gc[i] : gs[i - BSLICE_UINT4];
        }
        __syncthreads();

        if (w < 14) {
            uint4 Ae[2], Al[2], Ao[2], Az[2];
            #pragma unroll
            for (int mi = 0; mi < 2; mi++) {
                int mt = mgrp * 2 + mi;
                int ai = ((kt * 4 + mt) * 32 + lane) * 4;
                Ae[mi] = *(const uint4*)(a_ehi + ai);
                Al[mi] = *(const uint4*)(a_elo + ai);
                Ao[mi] = *(const uint4*)(a_ohi + ai);
                Az[mi] = *(const uint4*)(a_olo + ai);
            }
            #pragma unroll
            for (int t = 0; t < 4; t++) {
                int nt = nq * 4 + t;
                int bi = (nt * 32 + lane) * 4;
                uint4 bc = *(const uint4*)(s_b + bi);
                uint4 bs = *(const uint4*)(s_b + BSLICE_U32 + bi);
                #pragma unroll
                for (int mi = 0; mi < 2; mi++) {
                    MMA4(acc[mi][t],     Ae[mi].x, Ae[mi].y, Ae[mi].z, Ae[mi].w, bc.x, bc.y);
                    MMA4(acc[mi][t],     Al[mi].x, Al[mi].y, Al[mi].z, Al[mi].w, bc.x, bc.y);
                    MMA4(acc[mi][t],     Ae[mi].x, Ae[mi].y, Ae[mi].z, Ae[mi].w, bc.z, bc.w);
                    MMA4(acc[mi][t] + 4, Ao[mi].x, Ao[mi].y, Ao[mi].z, Ao[mi].w, bs.x, bs.y);
                    MMA4(acc[mi][t] + 4, Az[mi].x, Az[mi].y, Az[mi].z, Az[mi].w, bs.x, bs.y);
                    MMA4(acc[mi][t] + 4, Ao[mi].x, Ao[mi].y, Ao[mi].z, Ao[mi].w, bs.z, bs.w);
                }
            }
        }
    }
    __syncthreads();            // all MMA/staging done; s_b dies, s_p is born

    // ---- epilogue: DC/Nyquist terms + power into s_p ----
    if (w < 14) {
        #pragma unroll
        for (int mi = 0; mi < 2; mi++) {
            int mt  = mgrp * 2 + mi;
            int fa  = mt * 16 + (lane >> 2);
            int fb2 = fa + 8;
            float t0a   = s_w[0]   * s_raw[SWZ(fa  * HOP)];
            float t200a = s_w[200] * s_raw[SWZ(fa  * HOP + 200)];
            float t0b   = s_w[0]   * s_raw[SWZ(fb2 * HOP)];
            float t200b = s_w[200] * s_raw[SWZ(fb2 * HOP + 200)];
            #pragma unroll
            for (int t = 0; t < 4; t++) {
                int c0 = (nq * 4 + t) * 8 + ((lane & 3) << 1);
                float ra0 = acc[mi][t][0] + t0a + t200a;
                float ra1 = acc[mi][t][1] + t0a - t200a;
                float rb0 = acc[mi][t][2] + t0b + t200b;
                float rb1 = acc[mi][t][3] + t0b - t200b;
                if (c0 < NFREQ) {
                    s_p[fa  * PSTRIDE + c0] = ra0 * ra0 + acc[mi][t][4] * acc[mi][t][4];
                    s_p[fb2 * PSTRIDE + c0] = rb0 * rb0 + acc[mi][t][6] * acc[mi][t][6];
                }
                if (c0 + 1 < NFREQ) {
                    s_p[fa  * PSTRIDE + c0 + 1] = ra1 * ra1 + acc[mi][t][5] * acc[mi][t][5];
                    s_p[fb2 * PSTRIDE + c0 + 1] = rb1 * rb1 + acc[mi][t][7] * acc[mi][t][7];
                }
            }
        }
    }
    __syncthreads();

    // ---- sparse mel projection + log ----
    {
        const int f   = tid & (MTILE - 1);
        const int grp = tid >> 6;                 // 0..7
        int nvalid = NFRAMES - frame0;
        if (nvalid > MTILE) nvalid = MTILE;
        const float* prow = s_p + f * PSTRIDE;
        for (int m = grp; m < NMELS; m += 8) {
            int2 r = g_mrange[m];
            float acc2 = 0.0f;
            const float* fbr = fb + m * NFREQ;
            for (int kk = r.x; kk < r.y; kk++)
                acc2 = fmaf(fbr[kk], prow[kk], acc2);
            if (f < nvalid)
                out[((size_t)b * NMELS + m) * NFRAMES + frame0 + f] =
                    logf(acc2 + 1.1920929e-07f);
        }
    }
}

extern "C" void kernel_launch(void* const* d_in, const int* in_sizes, int n_in,
                              void* d_out, int out_size) {
    const float* audio  = (const float*)d_in[0];
    const float* window = (const float*)d_in[1];
    const float* fb     = (const float*)d_in[2];
    float* out          = (float*)d_out;

    cudaFuncSetAttribute(melspec_kernel,
                         cudaFuncAttributeMaxDynamicSharedMemorySize, SMEM_TOTAL);

    int setup_blocks = (2 * BTAB_U32 + 255) / 256 + 1;
    setup_kernel<<<setup_blocks, 256>>>(fb);

    dim3 grid(FBLK, NB);
    melspec_kernel<<<grid, NTHREADS, SMEM_TOTAL>>>(audio, window, fb, out);
}

// round 15
// speedup vs baseline: 1.4349x; 1.2481x over previous
#include <cuda_runtime.h>
#include <cuda_bf16.h>
#include <math.h>
#include <stdint.h>

// ---------------- problem constants ----------------
#define NB       128
#define TLEN     160000
#define NFFT     400
#define HOP      160
#define NFRAMES  1001
#define NFREQ    201
#define NMELS    80

// ---------------- GEMM tiling (mma.sync m16n8k16 bf16) ----------------
#define MTILE    64                  // frames per CTA
#define FBLK     16                  // CTAs per batch
#define KT       13                  // k16 tiles (K = 208, n = 1..199 padded)
#define NT       28                  // n8 tiles (bins padded to 224)
#define NTHREADS 896                 // 28 warps, all active in GEMM
#define SPAN     (HOP * (MTILE - 1) + NFFT)    // 10480
#define SWZ(i)   ((i) + ((i) >> 5))
#define PSTRIDE  209

// smem byte offsets
#define RAW_BYTES 43232              // SWZ(10479)+1 floats, padded
#define W_OFF    RAW_BYTES
#define A_OFF    (W_OFF + 1632)
#define APART_U32 (KT * 4 * 32 * 4)  // 6656 u32 per operand part
#define A_EHI    (A_OFF)
#define A_ELO    (A_EHI + APART_U32 * 4)
#define A_OHI    (A_ELO + APART_U32 * 4)
#define A_OLO    (A_OHI + APART_U32 * 4)
#define P_OFF    (A_OLO + APART_U32 * 4)
#define SMEM_TOTAL (P_OFF + MTILE * PSTRIDE * 4)   // 204864

// B tables in global, kt-major fragment layout:
// g_Bc/g_Bs[((kt*NT + nt)*32 + lane)*4 + r], r = {0,1}: hi regs, {2,3}: lo regs
#define BTAB_U32 (NT * KT * 32 * 4)            // 46592
__device__ unsigned g_Bc[BTAB_U32];
__device__ unsigned g_Bs[BTAB_U32];
__device__ int2 g_mrange[NMELS];

__device__ __forceinline__ void bf_split(float v, unsigned short& hi, unsigned short& lo) {
    __nv_bfloat16 h = __float2bfloat16(v);
    hi = __bfloat16_as_ushort(h);
    lo = __bfloat16_as_ushort(__float2bfloat16(v - __bfloat162float(h)));
}

// ---------------- setup: B fragments + mel ranges ----------------
__global__ void setup_kernel(const float* __restrict__ fb) {
    if (blockIdx.x == gridDim.x - 1) {
        int m = threadIdx.x;
        if (m < NMELS) {
            int ks = NFREQ, ke = 0;
            for (int k = 0; k < NFREQ; k++)
                if (fb[m * NFREQ + k] != 0.0f) { if (k < ks) ks = k; ke = k + 1; }
            if (ke < ks) { ks = 0; ke = 0; }
            g_mrange[m] = make_int2(ks, ke);
        }
        return;
    }
    int id = blockIdx.x * blockDim.x + threadIdx.x;
    if (id >= 2 * BTAB_U32) return;
    int trig = id / BTAB_U32;
    int s    = id - trig * BTAB_U32;
    int r    = s & 3;                  // 0,1: hi pair regs; 2,3: lo pair regs
    int lane = (s >> 2) & 31;
    int t    = s >> 7;
    int kt   = t % 13;
    int nt   = t / 13;
    int reg  = r & 1;
    int part_lo = r >> 1;
    int p    = (reg << 2) | (lane & 3);    // k-pair index within k16 tile
    int col  = lane >> 2;
    int k0   = kt * 16 + 2 * p;
    int bin  = nt * 8 + col;
    unsigned short b0 = 0, b1 = 0;
    #pragma unroll
    for (int e = 0; e < 2; e++) {
        int n = k0 + e + 1;
        float v = 0.0f;
        if (n <= 199 && bin <= 200) {
            long long ph = ((long long)n * bin) % NFFT;
            double a = (double)ph * (6.283185307179586476925286766559 / (double)NFFT);
            v = (float)(trig ? sin(a) : cos(a));
        }
        unsigned short hi, lo;
        bf_split(v, hi, lo);
        unsigned short ev = part_lo ? lo : hi;
        if (e == 0) b0 = ev; else b1 = ev;
    }
    int dst_idx = ((kt * NT + nt) * 32 + lane) * 4 + r;   // kt-major
    unsigned* dst = trig ? g_Bs : g_Bc;
    dst[dst_idx] = ((unsigned)b1 << 16) | b0;
}

#define MMA4(d, ax,ay,az,aw, bx,by) \
    asm volatile("mma.sync.aligned.m16n8k16.row.col.f32.bf16.bf16.f32 " \
        "{%0,%1,%2,%3}, {%4,%5,%6,%7}, {%8,%9}, {%0,%1,%2,%3};" \
        : "+f"((d)[0]), "+f"((d)[1]), "+f"((d)[2]), "+f"((d)[3]) \
        : "r"(ax), "r"(ay), "r"(az), "r"(aw), "r"(bx), "r"(by))

// ---------------- main kernel ----------------
__global__ __launch_bounds__(NTHREADS, 1)
void melspec_kernel(const float* __restrict__ audio,
                    const float* __restrict__ window,
                    const float* __restrict__ fb,
                    float* __restrict__ out) {
    extern __shared__ char smem[];
    float*    s_raw = (float*)smem;
    float*    s_w   = (float*)(smem + W_OFF);
    unsigned* a_ehi = (unsigned*)(smem + A_EHI);
    unsigned* a_elo = (unsigned*)(smem + A_ELO);
    unsigned* a_ohi = (unsigned*)(smem + A_OHI);
    unsigned* a_olo = (unsigned*)(smem + A_OLO);
    float*    s_p   = (float*)(smem + P_OFF);

    const int tid    = threadIdx.x;
    const int b      = blockIdx.y;
    const int frame0 = blockIdx.x * MTILE;
    const float* x   = audio + (size_t)b * TLEN;
    const int base   = frame0 * HOP - (NFFT / 2);

    // ---- raw samples (reflect pad, swizzled) + window ----
    for (int i = tid; i < SPAN; i += NTHREADS) {
        int j = base + i;
        if (j < 0) j = -j;
        else if (j >= TLEN) j = 2 * TLEN - 2 - j;
        s_raw[SWZ(i)] = x[j];
    }
    if (tid < NFFT) s_w[tid] = window[tid];
    __syncthreads();

    // ---- build A fragments: e/o, hi/lo, in mma lane layout ----
    for (int i = tid; i < MTILE * 104; i += NTHREADS) {
        int f  = i & 63;
        int kq = i >> 6;                 // 0..103
        int k0 = kq * 2;
        int nb = f * HOP;
        float e0 = 0.f, o0 = 0.f, e1 = 0.f, o1 = 0.f;
        int n0 = k0 + 1;
        if (n0 <= 199) {
            float w = s_w[n0];
            float a = s_raw[SWZ(nb + n0)], c = s_raw[SWZ(nb + NFFT - n0)];
            e0 = w * (a + c); o0 = w * (a - c);
        }
        int n1 = k0 + 2;
        if (n1 <= 199) {
            float w = s_w[n1];
            float a = s_raw[SWZ(nb + n1)], c = s_raw[SWZ(nb + NFFT - n1)];
            e1 = w * (a + c); o1 = w * (a - c);
        }
        unsigned short eh0, el0, eh1, el1, oh0, ol0, oh1, ol1;
        bf_split(e0, eh0, el0); bf_split(e1, eh1, el1);
        bf_split(o0, oh0, ol0); bf_split(o1, oh1, ol1);
        int kt   = k0 >> 4;
        int q    = (k0 >> 1) & 7;
        int lane = ((f & 7) << 2) | (q & 3);
        int reg  = ((f >> 3) & 1) | (((q >> 2) & 1) << 1);
        int mt   = f >> 4;
        int ai   = ((kt * 4 + mt) * 32 + lane) * 4 + reg;
        a_ehi[ai] = ((unsigned)eh1 << 16) | eh0;
        a_elo[ai] = ((unsigned)el1 << 16) | el0;
        a_ohi[ai] = ((unsigned)oh1 << 16) | oh0;
        a_olo[ai] = ((unsigned)ol1 << 16) | ol0;
    }
    __syncthreads();

    // ---- GEMM: 28 warps, 2 m-tiles x 2 n-tiles per warp, e/o phase-split ----
    const int w    = tid >> 5;           // 0..27, all active
    const int lane = tid & 31;
    const int mgrp = w & 1;              // m-tiles {2*mgrp, 2*mgrp+1}
    const int nq   = w >> 1;             // 0..13; n-tiles {2*nq, 2*nq+1}

    float acc[2][2][8];                  // [mi][t][0..3 re, 4..7 im]
    #pragma unroll
    for (int mi = 0; mi < 2; mi++)
        #pragma unroll
        for (int t = 0; t < 2; t++)
            #pragma unroll
            for (int j = 0; j < 8; j++) acc[mi][t][j] = 0.0f;

    for (int kt = 0; kt < KT; kt++) {
        const int ktbase = (kt * NT + nq * 2) * 128 + lane * 4;
        // --- cos passes (even combos) ---
        {
            uint4 Ae[2], Al[2];
            #pragma unroll
            for (int mi = 0; mi < 2; mi++) {
                int ai = ((kt * 4 + (mgrp * 2 + mi)) * 32 + lane) * 4;
                Ae[mi] = *(const uint4*)(a_ehi + ai);
                Al[mi] = *(const uint4*)(a_elo + ai);
            }
            #pragma unroll
            for (int t = 0; t < 2; t++) {
                uint4 bc = *(const uint4*)(g_Bc + ktbase + t * 128);
                #pragma unroll
                for (int mi = 0; mi < 2; mi++) {
                    MMA4(acc[mi][t], Ae[mi].x, Ae[mi].y, Ae[mi].z, Ae[mi].w, bc.x, bc.y);
                    MMA4(acc[mi][t], Al[mi].x, Al[mi].y, Al[mi].z, Al[mi].w, bc.x, bc.y);
                    MMA4(acc[mi][t], Ae[mi].x, Ae[mi].y, Ae[mi].z, Ae[mi].w, bc.z, bc.w);
                }
            }
        }
        // --- sin passes (odd combos), A registers reused ---
        {
            uint4 Ao[2], Az[2];
            #pragma unroll
            for (int mi = 0; mi < 2; mi++) {
                int ai = ((kt * 4 + (mgrp * 2 + mi)) * 32 + lane) * 4;
                Ao[mi] = *(const uint4*)(a_ohi + ai);
                Az[mi] = *(const uint4*)(a_olo + ai);
            }
            #pragma unroll
            for (int t = 0; t < 2; t++) {
                uint4 bs = *(const uint4*)(g_Bs + ktbase + t * 128);
                #pragma unroll
                for (int mi = 0; mi < 2; mi++) {
                    MMA4(acc[mi][t] + 4, Ao[mi].x, Ao[mi].y, Ao[mi].z, Ao[mi].w, bs.x, bs.y);
                    MMA4(acc[mi][t] + 4, Az[mi].x, Az[mi].y, Az[mi].z, Az[mi].w, bs.x, bs.y);
                    MMA4(acc[mi][t] + 4, Ao[mi].x, Ao[mi].y, Ao[mi].z, Ao[mi].w, bs.z, bs.w);
                }
            }
        }
    }

    // ---- epilogue: DC/Nyquist terms + power into s_p ----
    #pragma unroll
    for (int mi = 0; mi < 2; mi++) {
        int mt  = mgrp * 2 + mi;
        int fa  = mt * 16 + (lane >> 2);
        int fb2 = fa + 8;
        float t0a   = s_w[0]   * s_raw[SWZ(fa  * HOP)];
        float t200a = s_w[200] * s_raw[SWZ(fa  * HOP + 200)];
        float t0b   = s_w[0]   * s_raw[SWZ(fb2 * HOP)];
        float t200b = s_w[200] * s_raw[SWZ(fb2 * HOP + 200)];
        #pragma unroll
        for (int t = 0; t < 2; t++) {
            int c0 = (nq * 2 + t) * 8 + ((lane & 3) << 1);
            float ra0 = acc[mi][t][0] + t0a + t200a;
            float ra1 = acc[mi][t][1] + t0a - t200a;
            float rb0 = acc[mi][t][2] + t0b + t200b;
            float rb1 = acc[mi][t][3] + t0b - t200b;
            if (c0 < NFREQ) {
                s_p[fa  * PSTRIDE + c0] = ra0 * ra0 + acc[mi][t][4] * acc[mi][t][4];
                s_p[fb2 * PSTRIDE + c0] = rb0 * rb0 + acc[mi][t][6] * acc[mi][t][6];
            }
            if (c0 + 1 < NFREQ) {
                s_p[fa  * PSTRIDE + c0 + 1] = ra1 * ra1 + acc[mi][t][5] * acc[mi][t][5];
                s_p[fb2 * PSTRIDE + c0 + 1] = rb1 * rb1 + acc[mi][t][7] * acc[mi][t][7];
            }
        }
    }
    __syncthreads();

    // ---- sparse mel projection + log ----
    {
        const int f   = tid & (MTILE - 1);
        const int grp = tid >> 6;                 // 0..13
        int nvalid = NFRAMES - frame0;
        if (nvalid > MTILE) nvalid = MTILE;
        const float* prow = s_p + f * PSTRIDE;
        for (int m = grp; m < NMELS; m += NTHREADS / MTILE) {
            int2 r = g_mrange[m];
            float acc2 = 0.0f;
            const float* fbr = fb + m * NFREQ;
            for (int kk = r.x; kk < r.y; kk++)
                acc2 = fmaf(fbr[kk], prow[kk], acc2);
            if (f < nvalid)
                out[((size_t)b * NMELS + m) * NFRAMES + frame0 + f] =
                    logf(acc2 + 1.1920929e-07f);
        }
    }
}

extern "C" void kernel_launch(void* const* d_in, const int* in_sizes, int n_in,
                              void* d_out, int out_size) {
    const float* audio  = (const float*)d_in[0];
    const float* window = (const float*)d_in[1];
    const float* fb     = (const float*)d_in[2];
    float* out          = (float*)d_out;

    cudaFuncSetAttribute(melspec_kernel,
                         cudaFuncAttributeMaxDynamicSharedMemorySize, SMEM_TOTAL);

    int setup_blocks = (2 * BTAB_U32 + 255) / 256 + 1;
    setup_kernel<<<setup_blocks, 256>>>(fb);

    dim3 grid(FBLK, NB);
    melspec_kernel<<<grid, NTHREADS, SMEM_TOTAL>>>(audio, window, fb, out);
}

// round 17
// speedup vs baseline: 1.6580x; 1.1555x over previous
#include <cuda_runtime.h>
#include <cuda_bf16.h>
#include <math.h>
#include <stdint.h>

// ---------------- problem constants ----------------
#define NB       128
#define TLEN     160000
#define NFFT     400
#define HOP      160
#define NFRAMES  1001
#define NFREQ    201
#define NMELS    80

// ---------------- GEMM tiling (mma.sync m16n8k16 bf16) ----------------
#define MTILE    32                  // frames per CTA (2 m16-tiles)
#define FBLK     32                  // CTAs per batch (32*32 >= 1001)
#define KT       13                  // k16 tiles (K = 208, n = 1..199 padded)
#define NT       28                  // n8 tiles (bins padded to 224)
#define NTHREADS 448                 // 14 warps
#define SPAN     (HOP * (MTILE - 1) + NFFT)    // 5360
#define SWZ(i)   ((i) + ((i) >> 5))
#define PSTRIDE  209

// smem byte offsets (total must be <= 113 KB for 2 CTAs/SM)
#define RAW_BYTES 22112              // SWZ(5359)+1 = 5527 floats, padded
#define W_OFF    RAW_BYTES
#define A_OFF    (W_OFF + 1632)      // 23744
#define APART_U32 (KT * 2 * 32 * 4)  // 3328 u32 per operand part (2 m-tiles)
#define A_EHI    (A_OFF)
#define A_ELO    (A_EHI + APART_U32 * 4)
#define A_OHI    (A_ELO + APART_U32 * 4)
#define A_OLO    (A_OHI + APART_U32 * 4)
#define P_OFF    (A_OLO + APART_U32 * 4)       // 76992
#define SMEM_TOTAL (P_OFF + MTILE * PSTRIDE * 4)   // 103744

// B tables in global, kt-major fragment layout:
// g_Bc/g_Bs[((kt*NT + nt)*32 + lane)*4 + r], r = {0,1}: hi regs, {2,3}: lo regs
#define BTAB_U32 (NT * KT * 32 * 4)            // 46592
__device__ unsigned g_Bc[BTAB_U32];
__device__ unsigned g_Bs[BTAB_U32];
__device__ int2 g_mrange[NMELS];

__device__ __forceinline__ void bf_split(float v, unsigned short& hi, unsigned short& lo) {
    __nv_bfloat16 h = __float2bfloat16(v);
    hi = __bfloat16_as_ushort(h);
    lo = __bfloat16_as_ushort(__float2bfloat16(v - __bfloat162float(h)));
}

// ---------------- setup: B fragments + mel ranges ----------------
__global__ void setup_kernel(const float* __restrict__ fb) {
    if (blockIdx.x == gridDim.x - 1) {
        int m = threadIdx.x;
        if (m < NMELS) {
            int ks = NFREQ, ke = 0;
            for (int k = 0; k < NFREQ; k++)
                if (fb[m * NFREQ + k] != 0.0f) { if (k < ks) ks = k; ke = k + 1; }
            if (ke < ks) { ks = 0; ke = 0; }
            g_mrange[m] = make_int2(ks, ke);
        }
        return;
    }
    int id = blockIdx.x * blockDim.x + threadIdx.x;
    if (id >= 2 * BTAB_U32) return;
    int trig = id / BTAB_U32;
    int s    = id - trig * BTAB_U32;
    int r    = s & 3;                  // 0,1: hi pair regs; 2,3: lo pair regs
    int lane = (s >> 2) & 31;
    int t    = s >> 7;
    int kt   = t % 13;
    int nt   = t / 13;
    int reg  = r & 1;
    int part_lo = r >> 1;
    int p    = (reg << 2) | (lane & 3);    // k-pair index within k16 tile
    int col  = lane >> 2;
    int k0   = kt * 16 + 2 * p;
    int bin  = nt * 8 + col;
    unsigned short b0 = 0, b1 = 0;
    #pragma unroll
    for (int e = 0; e < 2; e++) {
        int n = k0 + e + 1;
        float v = 0.0f;
        if (n <= 199 && bin <= 200) {
            long long ph = ((long long)n * bin) % NFFT;
            double a = (double)ph * (6.283185307179586476925286766559 / (double)NFFT);
            v = (float)(trig ? sin(a) : cos(a));
        }
        unsigned short hi, lo;
        bf_split(v, hi, lo);
        unsigned short ev = part_lo ? lo : hi;
        if (e == 0) b0 = ev; else b1 = ev;
    }
    int dst_idx = ((kt * NT + nt) * 32 + lane) * 4 + r;   // kt-major
    unsigned* dst = trig ? g_Bs : g_Bc;
    dst[dst_idx] = ((unsigned)b1 << 16) | b0;
}

#define MMA4(d, ax,ay,az,aw, bx,by) \
    asm volatile("mma.sync.aligned.m16n8k16.row.col.f32.bf16.bf16.f32 " \
        "{%0,%1,%2,%3}, {%4,%5,%6,%7}, {%8,%9}, {%0,%1,%2,%3};" \
        : "+f"((d)[0]), "+f"((d)[1]), "+f"((d)[2]), "+f"((d)[3]) \
        : "r"(ax), "r"(ay), "r"(az), "r"(aw), "r"(bx), "r"(by))

// ---------------- main kernel ----------------
__global__ __launch_bounds__(NTHREADS, 2)
void melspec_kernel(const float* __restrict__ audio,
                    const float* __restrict__ window,
                    const float* __restrict__ fb,
                    float* __restrict__ out) {
    extern __shared__ char smem[];
    float*    s_raw = (float*)smem;
    float*    s_w   = (float*)(smem + W_OFF);
    unsigned* a_ehi = (unsigned*)(smem + A_EHI);
    unsigned* a_elo = (unsigned*)(smem + A_ELO);
    unsigned* a_ohi = (unsigned*)(smem + A_OHI);
    unsigned* a_olo = (unsigned*)(smem + A_OLO);
    float*    s_p   = (float*)(smem + P_OFF);

    const int tid    = threadIdx.x;
    const int b      = blockIdx.y;
    const int frame0 = blockIdx.x * MTILE;
    const float* x   = audio + (size_t)b * TLEN;
    const int base   = frame0 * HOP - (NFFT / 2);

    // ---- raw samples (reflect pad, swizzled) + window ----
    for (int i = tid; i < SPAN; i += NTHREADS) {
        int j = base + i;
        if (j < 0) j = -j;
        else if (j >= TLEN) j = 2 * TLEN - 2 - j;
        s_raw[SWZ(i)] = x[j];
    }
    if (tid < NFFT) s_w[tid] = window[tid];
    __syncthreads();

    // ---- build A fragments: e/o, hi/lo, in mma lane layout ----
    for (int i = tid; i < MTILE * 104; i += NTHREADS) {   // 3328 items
        int f  = i & (MTILE - 1);
        int kq = i >> 5;                 // 0..103
        int k0 = kq * 2;
        int nb = f * HOP;
        float e0 = 0.f, o0 = 0.f, e1 = 0.f, o1 = 0.f;
        int n0 = k0 + 1;
        if (n0 <= 199) {
            float w = s_w[n0];
            float a = s_raw[SWZ(nb + n0)], c = s_raw[SWZ(nb + NFFT - n0)];
            e0 = w * (a + c); o0 = w * (a - c);
        }
        int n1 = k0 + 2;
        if (n1 <= 199) {
            float w = s_w[n1];
            float a = s_raw[SWZ(nb + n1)], c = s_raw[SWZ(nb + NFFT - n1)];
            e1 = w * (a + c); o1 = w * (a - c);
        }
        unsigned short eh0, el0, eh1, el1, oh0, ol0, oh1, ol1;
        bf_split(e0, eh0, el0); bf_split(e1, eh1, el1);
        bf_split(o0, oh0, ol0); bf_split(o1, oh1, ol1);
        int kt   = k0 >> 4;
        int q    = (k0 >> 1) & 7;
        int lane = ((f & 7) << 2) | (q & 3);
        int reg  = ((f >> 3) & 1) | (((q >> 2) & 1) << 1);
        int mt   = f >> 4;               // 0..1
        int ai   = ((kt * 2 + mt) * 32 + lane) * 4 + reg;
        a_ehi[ai] = ((unsigned)eh1 << 16) | eh0;
        a_elo[ai] = ((unsigned)el1 << 16) | el0;
        a_ohi[ai] = ((unsigned)oh1 << 16) | oh0;
        a_olo[ai] = ((unsigned)ol1 << 16) | ol0;
    }
    __syncthreads();

    // ---- GEMM: 14 warps, each 2 m-tiles x 2 n-tiles, e/o phase-split ----
    const int w    = tid >> 5;           // 0..13 = nq
    const int lane = tid & 31;
    const int nq   = w;                  // n-tiles {2*nq, 2*nq+1}

    float acc[2][2][8];                  // [mi][t][0..3 re, 4..7 im]
    #pragma unroll
    for (int mi = 0; mi < 2; mi++)
        #pragma unroll
        for (int t = 0; t < 2; t++)
            #pragma unroll
            for (int j = 0; j < 8; j++) acc[mi][t][j] = 0.0f;

    for (int kt = 0; kt < KT; kt++) {
        const int ktbase = (kt * NT + nq * 2) * 128 + lane * 4;
        // --- cos passes (even combos) ---
        {
            uint4 Ae[2], Al[2];
            #pragma unroll
            for (int mi = 0; mi < 2; mi++) {
                int ai = ((kt * 2 + mi) * 32 + lane) * 4;
                Ae[mi] = *(const uint4*)(a_ehi + ai);
                Al[mi] = *(const uint4*)(a_elo + ai);
            }
            #pragma unroll
            for (int t = 0; t < 2; t++) {
                uint4 bc = *(const uint4*)(g_Bc + ktbase + t * 128);
                #pragma unroll
                for (int mi = 0; mi < 2; mi++) {
                    MMA4(acc[mi][t], Ae[mi].x, Ae[mi].y, Ae[mi].z, Ae[mi].w, bc.x, bc.y);
                    MMA4(acc[mi][t], Al[mi].x, Al[mi].y, Al[mi].z, Al[mi].w, bc.x, bc.y);
                    MMA4(acc[mi][t], Ae[mi].x, Ae[mi].y, Ae[mi].z, Ae[mi].w, bc.z, bc.w);
                }
            }
        }
        // --- sin passes (odd combos), A registers reused ---
        {
            uint4 Ao[2], Az[2];
            #pragma unroll
            for (int mi = 0; mi < 2; mi++) {
                int ai = ((kt * 2 + mi) * 32 + lane) * 4;
                Ao[mi] = *(const uint4*)(a_ohi + ai);
                Az[mi] = *(const uint4*)(a_olo + ai);
            }
            #pragma unroll
            for (int t = 0; t < 2; t++) {
                uint4 bs = *(const uint4*)(g_Bs + ktbase + t * 128);
                #pragma unroll
                for (int mi = 0; mi < 2; mi++) {
                    MMA4(acc[mi][t] + 4, Ao[mi].x, Ao[mi].y, Ao[mi].z, Ao[mi].w, bs.x, bs.y);
                    MMA4(acc[mi][t] + 4, Az[mi].x, Az[mi].y, Az[mi].z, Az[mi].w, bs.x, bs.y);
                    MMA4(acc[mi][t] + 4, Ao[mi].x, Ao[mi].y, Ao[mi].z, Ao[mi].w, bs.z, bs.w);
                }
            }
        }
    }

    // ---- epilogue: DC/Nyquist terms + power into s_p ----
    #pragma unroll
    for (int mi = 0; mi < 2; mi++) {
        int fa  = mi * 16 + (lane >> 2);
        int fb2 = fa + 8;
        float t0a   = s_w[0]   * s_raw[SWZ(fa  * HOP)];
        float t200a = s_w[200] * s_raw[SWZ(fa  * HOP + 200)];
        float t0b   = s_w[0]   * s_raw[SWZ(fb2 * HOP)];
        float t200b = s_w[200] * s_raw[SWZ(fb2 * HOP + 200)];
        #pragma unroll
        for (int t = 0; t < 2; t++) {
            int c0 = (nq * 2 + t) * 8 + ((lane & 3) << 1);
            float ra0 = acc[mi][t][0] + t0a + t200a;
            float ra1 = acc[mi][t][1] + t0a - t200a;
            float rb0 = acc[mi][t][2] + t0b + t200b;
            float rb1 = acc[mi][t][3] + t0b - t200b;
            if (c0 < NFREQ) {
                s_p[fa  * PSTRIDE + c0] = ra0 * ra0 + acc[mi][t][4] * acc[mi][t][4];
                s_p[fb2 * PSTRIDE + c0] = rb0 * rb0 + acc[mi][t][6] * acc[mi][t][6];
            }
            if (c0 + 1 < NFREQ) {
                s_p[fa  * PSTRIDE + c0 + 1] = ra1 * ra1 + acc[mi][t][5] * acc[mi][t][5];
                s_p[fb2 * PSTRIDE + c0 + 1] = rb1 * rb1 + acc[mi][t][7] * acc[mi][t][7];
            }
        }
    }
    __syncthreads();

    // ---- sparse mel projection + log ----
    {
        const int f   = tid & (MTILE - 1);
        const int grp = tid >> 5;                 // 0..13
        int nvalid = NFRAMES - frame0;
        if (nvalid > MTILE) nvalid = MTILE;
        const float* prow = s_p + f * PSTRIDE;
        for (int m = grp; m < NMELS; m += NTHREADS / MTILE) {
            int2 r = g_mrange[m];
            float acc2 = 0.0f;
            const float* fbr = fb + m * NFREQ;
            for (int kk = r.x; kk < r.y; kk++)
                acc2 = fmaf(fbr[kk], prow[kk], acc2);
            if (f < nvalid)
                out[((size_t)b * NMELS + m) * NFRAMES + frame0 + f] =
                    logf(acc2 + 1.1920929e-07f);
        }
    }
}

extern "C" void kernel_launch(void* const* d_in, const int* in_sizes, int n_in,
                              void* d_out, int out_size) {
    const float* audio  = (const float*)d_in[0];
    const float* window = (const float*)d_in[1];
    const float* fb     = (const float*)d_in[2];
    float* out          = (float*)d_out;

    cudaFuncSetAttribute(melspec_kernel,
                         cudaFuncAttributeMaxDynamicSharedMemorySize, SMEM_TOTAL);

    int setup_blocks = (2 * BTAB_U32 + 255) / 256 + 1;
    setup_kernel<<<setup_blocks, 256>>>(fb);

    dim3 grid(FBLK, NB);
    melspec_kernel<<<grid, NTHREADS, SMEM_TOTAL>>>(audio, window, fb, out);
}